// round 9
// baseline (speedup 1.0000x reference)
#include <cuda_runtime.h>
#include <cuda_fp16.h>
#include <cstdint>

// support: (2,5,1024,128) -> d_in[0]
// query:   (2,4,1024,128) -> d_in[1]
// out:     (2,4,5,1024,1024) fp32
// sim[b,i,j,m,n] = <q_norm[b,i,m,:], s_norm[b,j,n,:]>
//
// fp16 2-pass error compensation: A (query) split into fp16 hi+lo,
// B (support) rounded to fp16. D = Ah*Bh + Al*Bh, values scaled by 32,
// epilogue divides by 1024.
// CTA tile 256x128, 8 warps as 4(m)x2(n), warp tile 64x64 -> 33% less
// LDSM traffic per output than 64x32. Double-buffered cp.async, 96KB smem.

#define NQ_ROWS 8192
#define NS_ROWS 10240
#define KDIM 128
#define KSPLIT 256   // A rows: [hi(128) | lo(128)] fp16
#define SCALE 32.0f
#define INV_SCALE2 (1.0f / 1024.0f)

__device__ __align__(16) __half g_qs[NQ_ROWS * KSPLIT];
__device__ __align__(16) __half g_ss[NS_ROWS * KDIM];   // hi only

__device__ __forceinline__ uint32_t smem_u32(const void* p) {
    uint32_t a;
    asm("{ .reg .u64 t; cvta.to.shared.u64 t, %1; cvt.u32.u64 %0, t; }"
        : "=r"(a) : "l"(p));
    return a;
}

__device__ __forceinline__ void ldm_x4(uint32_t* r, uint32_t addr) {
    asm volatile("ldmatrix.sync.aligned.m8n8.x4.shared.b16 {%0,%1,%2,%3}, [%4];"
        : "=r"(r[0]), "=r"(r[1]), "=r"(r[2]), "=r"(r[3]) : "r"(addr));
}

__device__ __forceinline__ void mma16816(float* d, const uint32_t* a,
                                         const uint32_t* b) {
    asm volatile(
        "mma.sync.aligned.m16n8k16.row.col.f32.f16.f16.f32 "
        "{%0,%1,%2,%3}, {%4,%5,%6,%7}, {%8,%9}, {%0,%1,%2,%3};"
        : "+f"(d[0]), "+f"(d[1]), "+f"(d[2]), "+f"(d[3])
        : "r"(a[0]), "r"(a[1]), "r"(a[2]), "r"(a[3]), "r"(b[0]), "r"(b[1]));
}

#define CP_ASYNC16(dst, src) \
    asm volatile("cp.async.cg.shared.global [%0], [%1], 16;" \
        :: "r"(dst), "l"(src) : "memory")
#define CP_COMMIT() asm volatile("cp.async.commit_group;" ::: "memory")
#define CP_WAIT(n)  asm volatile("cp.async.wait_group %0;" :: "n"(n) : "memory")

// ---------------------------------------------------------------------------
// Kernel 1: normalize rows; query -> fp16 hi/lo (scaled), support -> fp16.
// ---------------------------------------------------------------------------
__global__ void normalize_split_kernel(const float* __restrict__ s,
                                       const float* __restrict__ q) {
    int warp_id = (blockIdx.x * blockDim.x + threadIdx.x) >> 5;
    int lane    = threadIdx.x & 31;
    if (warp_id >= NQ_ROWS + NS_ROWS) return;

    bool is_q = warp_id < NQ_ROWS;
    const float* src = is_q ? q + (size_t)warp_id * KDIM
                            : s + (size_t)(warp_id - NQ_ROWS) * KDIM;

    float4 v = reinterpret_cast<const float4*>(src)[lane];
    float ssum = v.x * v.x + v.y * v.y + v.z * v.z + v.w * v.w;
    #pragma unroll
    for (int o = 16; o > 0; o >>= 1)
        ssum += __shfl_xor_sync(0xffffffffu, ssum, o);
    float rn = SCALE / fmaxf(sqrtf(ssum), 1e-12f);

    float f[4] = {v.x * rn, v.y * rn, v.z * rn, v.w * rn};
    __half h[4];
    #pragma unroll
    for (int e = 0; e < 4; e++) h[e] = __float2half_rn(f[e]);

    if (is_q) {
        __half* dst = g_qs + (size_t)warp_id * KSPLIT;
        __half l[4];
        #pragma unroll
        for (int e = 0; e < 4; e++)
            l[e] = __float2half_rn(f[e] - __half2float(h[e]));
        *reinterpret_cast<uint2*>(dst + lane * 4)       = *reinterpret_cast<uint2*>(h);
        *reinterpret_cast<uint2*>(dst + 128 + lane * 4) = *reinterpret_cast<uint2*>(l);
    } else {
        __half* dst = g_ss + (size_t)(warp_id - NQ_ROWS) * KDIM;
        *reinterpret_cast<uint2*>(dst + lane * 4) = *reinterpret_cast<uint2*>(h);
    }
}

// ---------------------------------------------------------------------------
// Kernel 2: pipelined HMMA GEMM. CTA tile 256x128, 8 warps 4(m)x2(n),
// warp tile 64x64. 4 macro-steps of K64: (Ah c0,B c0),(Ah c1,B c1),
// (Al c0,B c0),(Al c1,B c1). Stage = A 32KB + B 16KB, double buffered.
// Rows 64 fp16 = 128B, 16B-chunk XOR swizzle (ch ^ (row&7)).
// ---------------------------------------------------------------------------
#define CHUNK_A 32768   // 256 rows x 64 fp16
#define CHUNK_B 16384   // 128 rows x 64 fp16
#define BUF_BYTES (CHUNK_A + CHUNK_B)   // 48KB
#define SMEM_BYTES (2 * BUF_BYTES)      // 96KB

__global__ __launch_bounds__(256, 1)
void cosine_hmma_kernel(float* __restrict__ out) {
    extern __shared__ __align__(1024) char smem[];

    int tid  = threadIdx.x;
    int wid  = tid >> 5;
    int lane = tid & 31;

    int p  = blockIdx.z;          // (b*4+i)*5 + j
    int b  = p / 20;
    int ij = p % 20;
    int i  = ij / 5;
    int j  = ij % 5;
    int m0 = blockIdx.y * 256;
    int n0 = blockIdx.x * 128;

    const __half* abase = g_qs + (size_t)((b * 4 + i) * 1024 + m0) * KSPLIT;
    const __half* bbase = g_ss + (size_t)((b * 5 + j) * 1024 + n0) * KDIM;

    const int ACOL[4] = {0, 64, 128, 192};  // hi c0, hi c1, lo c0, lo c1
    const int BCOL[4] = {0, 64, 0, 64};

    uint32_t smem0 = smem_u32(smem);

    auto load_step = [&](int s) {
        uint32_t bufA = smem0 + (uint32_t)(s & 1) * BUF_BYTES;
        uint32_t bufB = bufA + CHUNK_A;
        int ac = ACOL[s], bc = BCOL[s];
        // A: 2048 chunks of 16B (256 rows x 8 chunks)
        #pragma unroll
        for (int it = 0; it < 8; it++) {
            int lin = tid + it * 256;    // 0..2047
            int row = lin >> 3;          // 0..255
            int ch  = lin & 7;
            uint32_t doff = (uint32_t)row * 128u + (uint32_t)((ch ^ (row & 7)) << 4);
            CP_ASYNC16(bufA + doff, abase + (size_t)row * KSPLIT + ac + ch * 8);
        }
        // B: 1024 chunks (128 rows x 8 chunks)
        #pragma unroll
        for (int it = 0; it < 4; it++) {
            int lin = tid + it * 256;    // 0..1023
            int row = lin >> 3;          // 0..127
            int ch  = lin & 7;
            uint32_t doff = (uint32_t)row * 128u + (uint32_t)((ch ^ (row & 7)) << 4);
            CP_ASYNC16(bufB + doff, bbase + (size_t)row * KDIM + bc + ch * 8);
        }
        CP_COMMIT();
    };

    // ---- warp tiling: 4 warps over m (64 each), 2 over n (64 each) ----
    int wm = wid >> 1;
    int wn = wid & 1;
    int mbase = wm * 64;
    int nbase = wn * 64;

    int a_mi   = lane >> 3;
    int a_row0 = mbase + (a_mi & 1) * 8 + (lane & 7);         // + mt*16
    int a_koff = (a_mi >> 1) * 8;
    int b_row0 = nbase + ((lane >> 4) & 1) * 8 + (lane & 7);  // + nt2*16
    int b_koff = ((lane >> 3) & 1) * 8;

    float acc[4][8][4];
    #pragma unroll
    for (int mt = 0; mt < 4; mt++)
        #pragma unroll
        for (int nt = 0; nt < 8; nt++)
            #pragma unroll
            for (int e = 0; e < 4; e++)
                acc[mt][nt][e] = 0.0f;

    load_step(0);

    #pragma unroll
    for (int s = 0; s < 4; s++) {
        if (s + 1 < 4) {
            load_step(s + 1);
            CP_WAIT(1);
        } else {
            CP_WAIT(0);
        }
        __syncthreads();

        uint32_t bufA = smem0 + (uint32_t)(s & 1) * BUF_BYTES;
        uint32_t bufB = bufA + CHUNK_A;

        #pragma unroll
        for (int ks = 0; ks < 4; ks++) {
            int ka = ks * 16 + a_koff;
            int kb = ks * 16 + b_koff;

            uint32_t aF[4][4];
            #pragma unroll
            for (int mt = 0; mt < 4; mt++) {
                int row = a_row0 + mt * 16;
                uint32_t addr = bufA + (uint32_t)row * 128u
                              + (uint32_t)((((ka >> 3) ^ (row & 7)) << 4));
                ldm_x4(aF[mt], addr);
            }
            uint32_t bF[4][4];
            #pragma unroll
            for (int nt2 = 0; nt2 < 4; nt2++) {
                int row = b_row0 + nt2 * 16;
                uint32_t addr = bufB + (uint32_t)row * 128u
                              + (uint32_t)((((kb >> 3) ^ (row & 7)) << 4));
                ldm_x4(bF[nt2], addr);
            }

            #pragma unroll
            for (int mt = 0; mt < 4; mt++)
                #pragma unroll
                for (int nt = 0; nt < 8; nt++)
                    mma16816(acc[mt][nt], aF[mt], &bF[nt >> 1][(nt & 1) * 2]);
        }
        __syncthreads();
    }

    // ---- Epilogue: scale by 1/1024, direct fragment stores ----
    int tr  = lane >> 2;
    int tc2 = (lane & 3) * 2;
    size_t obase = ((size_t)p << 20)
                 + (size_t)(m0 + mbase) * 1024 + (n0 + nbase);
    #pragma unroll
    for (int mt = 0; mt < 4; mt++) {
        #pragma unroll
        for (int nt = 0; nt < 8; nt++) {
            float* r0 = out + obase + (size_t)(mt * 16 + tr) * 1024 + nt * 8 + tc2;
            *reinterpret_cast<float2*>(r0) =
                make_float2(acc[mt][nt][0] * INV_SCALE2, acc[mt][nt][1] * INV_SCALE2);
            *reinterpret_cast<float2*>(r0 + 8 * 1024) =
                make_float2(acc[mt][nt][2] * INV_SCALE2, acc[mt][nt][3] * INV_SCALE2);
        }
    }
}

extern "C" void kernel_launch(void* const* d_in, const int* in_sizes, int n_in,
                              void* d_out, int out_size) {
    const float* support = (const float*)d_in[0];
    const float* query   = (const float*)d_in[1];
    float* out = (float*)d_out;

    cudaFuncSetAttribute(cosine_hmma_kernel,
                         cudaFuncAttributeMaxDynamicSharedMemorySize, SMEM_BYTES);

    int total_rows = NQ_ROWS + NS_ROWS;
    int blocks1 = (total_rows + 7) / 8;
    normalize_split_kernel<<<blocks1, 256>>>(support, query);

    dim3 grid(8, 4, 40);
    cosine_hmma_kernel<<<grid, 256, SMEM_BYTES>>>(out);
}

// round 10
// speedup vs baseline: 1.1696x; 1.1696x over previous
#include <cuda_runtime.h>
#include <cuda_fp16.h>
#include <cstdint>

// support: (2,5,1024,128) -> d_in[0]
// query:   (2,4,1024,128) -> d_in[1]
// out:     (2,4,5,1024,1024) fp32
// sim[b,i,j,m,n] = <q_norm[b,i,m,:], s_norm[b,j,n,:]>
//
// fp16 2-pass error compensation: A (query) split into fp16 hi+lo,
// B (support) rounded to fp16. D = Ah*Bh + Al*Bh, values scaled by 32,
// epilogue divides by 1024.
// CTA tile 128x128, 8 warps 2(m)x4(n), warp 64x32. 4 macro-steps of K64,
// 3-buffer circular cp.async pipeline (2-deep prefetch, ONE sync/stage),
// 96KB smem/CTA -> 2 CTAs/SM.

#define NQ_ROWS 8192
#define NS_ROWS 10240
#define KDIM 128
#define KSPLIT 256   // A rows: [hi(128) | lo(128)] fp16
#define SCALE 32.0f
#define INV_SCALE2 (1.0f / 1024.0f)

__device__ __align__(16) __half g_qs[NQ_ROWS * KSPLIT];
__device__ __align__(16) __half g_ss[NS_ROWS * KDIM];   // hi only

__device__ __forceinline__ uint32_t smem_u32(const void* p) {
    uint32_t a;
    asm("{ .reg .u64 t; cvta.to.shared.u64 t, %1; cvt.u32.u64 %0, t; }"
        : "=r"(a) : "l"(p));
    return a;
}

__device__ __forceinline__ void ldm_x4(uint32_t* r, uint32_t addr) {
    asm volatile("ldmatrix.sync.aligned.m8n8.x4.shared.b16 {%0,%1,%2,%3}, [%4];"
        : "=r"(r[0]), "=r"(r[1]), "=r"(r[2]), "=r"(r[3]) : "r"(addr));
}

__device__ __forceinline__ void mma16816(float* d, const uint32_t* a,
                                         const uint32_t* b) {
    asm volatile(
        "mma.sync.aligned.m16n8k16.row.col.f32.f16.f16.f32 "
        "{%0,%1,%2,%3}, {%4,%5,%6,%7}, {%8,%9}, {%0,%1,%2,%3};"
        : "+f"(d[0]), "+f"(d[1]), "+f"(d[2]), "+f"(d[3])
        : "r"(a[0]), "r"(a[1]), "r"(a[2]), "r"(a[3]), "r"(b[0]), "r"(b[1]));
}

#define CP_ASYNC16(dst, src) \
    asm volatile("cp.async.cg.shared.global [%0], [%1], 16;" \
        :: "r"(dst), "l"(src) : "memory")
#define CP_COMMIT() asm volatile("cp.async.commit_group;" ::: "memory")
#define CP_WAIT(n)  asm volatile("cp.async.wait_group %0;" :: "n"(n) : "memory")

// ---------------------------------------------------------------------------
// Kernel 1: normalize rows; query -> fp16 hi/lo (scaled), support -> fp16.
// ---------------------------------------------------------------------------
__global__ void normalize_split_kernel(const float* __restrict__ s,
                                       const float* __restrict__ q) {
    int warp_id = (blockIdx.x * blockDim.x + threadIdx.x) >> 5;
    int lane    = threadIdx.x & 31;
    if (warp_id >= NQ_ROWS + NS_ROWS) return;

    bool is_q = warp_id < NQ_ROWS;
    const float* src = is_q ? q + (size_t)warp_id * KDIM
                            : s + (size_t)(warp_id - NQ_ROWS) * KDIM;

    float4 v = reinterpret_cast<const float4*>(src)[lane];
    float ssum = v.x * v.x + v.y * v.y + v.z * v.z + v.w * v.w;
    #pragma unroll
    for (int o = 16; o > 0; o >>= 1)
        ssum += __shfl_xor_sync(0xffffffffu, ssum, o);
    float rn = SCALE / fmaxf(sqrtf(ssum), 1e-12f);

    float f[4] = {v.x * rn, v.y * rn, v.z * rn, v.w * rn};
    __half h[4];
    #pragma unroll
    for (int e = 0; e < 4; e++) h[e] = __float2half_rn(f[e]);

    if (is_q) {
        __half* dst = g_qs + (size_t)warp_id * KSPLIT;
        __half l[4];
        #pragma unroll
        for (int e = 0; e < 4; e++)
            l[e] = __float2half_rn(f[e] - __half2float(h[e]));
        *reinterpret_cast<uint2*>(dst + lane * 4)       = *reinterpret_cast<uint2*>(h);
        *reinterpret_cast<uint2*>(dst + 128 + lane * 4) = *reinterpret_cast<uint2*>(l);
    } else {
        __half* dst = g_ss + (size_t)(warp_id - NQ_ROWS) * KDIM;
        *reinterpret_cast<uint2*>(dst + lane * 4) = *reinterpret_cast<uint2*>(h);
    }
}

// ---------------------------------------------------------------------------
// Kernel 2: pipelined HMMA GEMM. CTA 128x128, warp 64x32 (2m x 4n).
// Macro-steps (K64): s0=(Ah c0, B c0), s1=(Ah c1, B c1),
//                    s2=(Al c0, B c0), s3=(Al c1, B c1).
// 3 circular buffers of 32KB. Rows 64 fp16 = 128B, XOR swizzle ch^(row&7).
// ---------------------------------------------------------------------------
#define CHUNK_A 16384
#define CHUNK_B 16384
#define BUF_BYTES (CHUNK_A + CHUNK_B)   // 32KB per stage
#define NBUF 3
#define SMEM_BYTES (NBUF * BUF_BYTES)   // 96KB

__global__ __launch_bounds__(256, 2)
void cosine_hmma_kernel(float* __restrict__ out) {
    extern __shared__ __align__(1024) char smem[];

    int tid  = threadIdx.x;
    int wid  = tid >> 5;
    int lane = tid & 31;

    int p  = blockIdx.z;          // (b*4+i)*5 + j
    int b  = p / 20;
    int ij = p % 20;
    int i  = ij / 5;
    int j  = ij % 5;
    int m0 = blockIdx.y * 128;
    int n0 = blockIdx.x * 128;

    const __half* abase = g_qs + (size_t)((b * 4 + i) * 1024 + m0) * KSPLIT;
    const __half* bbase = g_ss + (size_t)((b * 5 + j) * 1024 + n0) * KDIM;

    const int ACOL[4] = {0, 64, 128, 192};  // hi c0, hi c1, lo c0, lo c1
    const int BCOL[4] = {0, 64, 0, 64};

    uint32_t smem0 = smem_u32(smem);

    auto load_step = [&](int s) {
        uint32_t bufA = smem0 + (uint32_t)(s % NBUF) * BUF_BYTES;
        uint32_t bufB = bufA + CHUNK_A;
        int ac = ACOL[s], bc = BCOL[s];
        #pragma unroll
        for (int it = 0; it < 4; it++) {
            int lin = tid + it * 256;    // 0..1023
            int row = lin >> 3;          // 0..127
            int ch  = lin & 7;           // 16B chunks of 128B row
            uint32_t doff = (uint32_t)row * 128u + (uint32_t)((ch ^ (row & 7)) << 4);
            CP_ASYNC16(bufA + doff, abase + (size_t)row * KSPLIT + ac + ch * 8);
            CP_ASYNC16(bufB + doff, bbase + (size_t)row * KDIM + bc + ch * 8);
        }
        CP_COMMIT();
    };

    // ---- warp tiling: 2 warps over m (64), 4 over n (32) ----
    int wm = wid & 1;
    int wn = wid >> 1;
    int mbase = wm * 64;
    int nbase = wn * 32;

    int a_mi   = lane >> 3;
    int a_row0 = mbase + (a_mi & 1) * 8 + (lane & 7);         // + mt*16
    int a_koff = (a_mi >> 1) * 8;
    int b_row0 = nbase + ((lane >> 4) & 1) * 8 + (lane & 7);  // + nt2*16
    int b_koff = ((lane >> 3) & 1) * 8;

    float acc[4][4][4];
    #pragma unroll
    for (int mt = 0; mt < 4; mt++)
        #pragma unroll
        for (int nt = 0; nt < 4; nt++)
            #pragma unroll
            for (int e = 0; e < 4; e++)
                acc[mt][nt][e] = 0.0f;

    auto mma_stage = [&](int s) {
        uint32_t bufA = smem0 + (uint32_t)(s % NBUF) * BUF_BYTES;
        uint32_t bufB = bufA + CHUNK_A;
        #pragma unroll
        for (int ks = 0; ks < 4; ks++) {
            int ka = ks * 16 + a_koff;
            int kb = ks * 16 + b_koff;

            uint32_t aF[4][4];
            #pragma unroll
            for (int mt = 0; mt < 4; mt++) {
                int row = a_row0 + mt * 16;
                uint32_t addr = bufA + (uint32_t)row * 128u
                              + (uint32_t)((((ka >> 3) ^ (row & 7)) << 4));
                ldm_x4(aF[mt], addr);
            }
            uint32_t bF[2][4];
            #pragma unroll
            for (int nt2 = 0; nt2 < 2; nt2++) {
                int row = b_row0 + nt2 * 16;
                uint32_t addr = bufB + (uint32_t)row * 128u
                              + (uint32_t)((((kb >> 3) ^ (row & 7)) << 4));
                ldm_x4(bF[nt2], addr);
            }

            #pragma unroll
            for (int mt = 0; mt < 4; mt++)
                #pragma unroll
                for (int nt = 0; nt < 4; nt++)
                    mma16816(acc[mt][nt], aF[mt], &bF[nt >> 1][(nt & 1) * 2]);
        }
    };

    // ---- 3-deep circular pipeline, one sync per stage ----
    load_step(0);
    load_step(1);
    load_step(2);

    // s=0: groups in flight {0,1,2}; need 0 done.
    CP_WAIT(2);
    __syncthreads();
    mma_stage(0);

    // s=1: need 1 done (outstanding {1,2}); after sync every warp has
    // finished MMA(0), so buf0 may be overwritten by load(3).
    CP_WAIT(1);
    __syncthreads();
    load_step(3);
    mma_stage(1);

    // s=2: outstanding {2,3}; need 2 done.
    CP_WAIT(1);
    __syncthreads();
    mma_stage(2);

    // s=3: need all done.
    CP_WAIT(0);
    __syncthreads();
    mma_stage(3);

    // ---- Epilogue: scale by 1/1024, direct fragment stores ----
    int tr  = lane >> 2;
    int tc2 = (lane & 3) * 2;
    size_t obase = ((size_t)p << 20)
                 + (size_t)(m0 + mbase) * 1024 + (n0 + nbase);
    #pragma unroll
    for (int mt = 0; mt < 4; mt++) {
        #pragma unroll
        for (int nt = 0; nt < 4; nt++) {
            float* r0 = out + obase + (size_t)(mt * 16 + tr) * 1024 + nt * 8 + tc2;
            *reinterpret_cast<float2*>(r0) =
                make_float2(acc[mt][nt][0] * INV_SCALE2, acc[mt][nt][1] * INV_SCALE2);
            *reinterpret_cast<float2*>(r0 + 8 * 1024) =
                make_float2(acc[mt][nt][2] * INV_SCALE2, acc[mt][nt][3] * INV_SCALE2);
        }
    }
}

extern "C" void kernel_launch(void* const* d_in, const int* in_sizes, int n_in,
                              void* d_out, int out_size) {
    const float* support = (const float*)d_in[0];
    const float* query   = (const float*)d_in[1];
    float* out = (float*)d_out;

    cudaFuncSetAttribute(cosine_hmma_kernel,
                         cudaFuncAttributeMaxDynamicSharedMemorySize, SMEM_BYTES);

    int total_rows = NQ_ROWS + NS_ROWS;
    int blocks1 = (total_rows + 7) / 8;
    normalize_split_kernel<<<blocks1, 256>>>(support, query);

    dim3 grid(8, 8, 40);
    cosine_hmma_kernel<<<grid, 256, SMEM_BYTES>>>(out);
}

// round 11
// speedup vs baseline: 1.4970x; 1.2800x over previous
#include <cuda_runtime.h>
#include <cuda_fp16.h>
#include <cstdint>

// support: (2,5,1024,128) -> d_in[0]
// query:   (2,4,1024,128) -> d_in[1]
// out:     (2,4,5,1024,1024) fp32
// sim[b,i,j,m,n] = <q_norm[b,i,m,:], s_norm[b,j,n,:]>
//
// Single-pass fp16 HMMA: normalized q and s rounded to fp16 once.
// Error = dq*s + q*ds ~ sqrt(2) * 2.07e-4 (measured one-sided) ~ 2.9e-4,
// comfortably under the 1e-3 threshold.
// CTA tile 128x128, 8 warps 2(m)x4(n), warp 64x32. 2 macro-steps of K64,
// double-buffered cp.async (one sync per stage), 64KB smem -> 2 CTAs/SM.

#define NQ_ROWS 8192
#define NS_ROWS 10240
#define KDIM 128

__device__ __align__(16) __half g_qs[NQ_ROWS * KDIM];
__device__ __align__(16) __half g_ss[NS_ROWS * KDIM];

__device__ __forceinline__ uint32_t smem_u32(const void* p) {
    uint32_t a;
    asm("{ .reg .u64 t; cvta.to.shared.u64 t, %1; cvt.u32.u64 %0, t; }"
        : "=r"(a) : "l"(p));
    return a;
}

__device__ __forceinline__ void ldm_x4(uint32_t* r, uint32_t addr) {
    asm volatile("ldmatrix.sync.aligned.m8n8.x4.shared.b16 {%0,%1,%2,%3}, [%4];"
        : "=r"(r[0]), "=r"(r[1]), "=r"(r[2]), "=r"(r[3]) : "r"(addr));
}

__device__ __forceinline__ void mma16816(float* d, const uint32_t* a,
                                         const uint32_t* b) {
    asm volatile(
        "mma.sync.aligned.m16n8k16.row.col.f32.f16.f16.f32 "
        "{%0,%1,%2,%3}, {%4,%5,%6,%7}, {%8,%9}, {%0,%1,%2,%3};"
        : "+f"(d[0]), "+f"(d[1]), "+f"(d[2]), "+f"(d[3])
        : "r"(a[0]), "r"(a[1]), "r"(a[2]), "r"(a[3]), "r"(b[0]), "r"(b[1]));
}

#define CP_ASYNC16(dst, src) \
    asm volatile("cp.async.cg.shared.global [%0], [%1], 16;" \
        :: "r"(dst), "l"(src) : "memory")
#define CP_COMMIT() asm volatile("cp.async.commit_group;" ::: "memory")
#define CP_WAIT(n)  asm volatile("cp.async.wait_group %0;" :: "n"(n) : "memory")

// ---------------------------------------------------------------------------
// Kernel 1: normalize rows -> fp16. One warp per row.
// ---------------------------------------------------------------------------
__global__ void normalize_kernel(const float* __restrict__ s,
                                 const float* __restrict__ q) {
    int warp_id = (blockIdx.x * blockDim.x + threadIdx.x) >> 5;
    int lane    = threadIdx.x & 31;
    if (warp_id >= NQ_ROWS + NS_ROWS) return;

    bool is_q = warp_id < NQ_ROWS;
    const float* src = is_q ? q + (size_t)warp_id * KDIM
                            : s + (size_t)(warp_id - NQ_ROWS) * KDIM;
    __half* dst = is_q ? g_qs + (size_t)warp_id * KDIM
                       : g_ss + (size_t)(warp_id - NQ_ROWS) * KDIM;

    float4 v = reinterpret_cast<const float4*>(src)[lane];
    float ssum = v.x * v.x + v.y * v.y + v.z * v.z + v.w * v.w;
    #pragma unroll
    for (int o = 16; o > 0; o >>= 1)
        ssum += __shfl_xor_sync(0xffffffffu, ssum, o);
    float rn = 1.0f / fmaxf(sqrtf(ssum), 1e-12f);

    __half h[4] = {__float2half_rn(v.x * rn), __float2half_rn(v.y * rn),
                   __float2half_rn(v.z * rn), __float2half_rn(v.w * rn)};
    *reinterpret_cast<uint2*>(dst + lane * 4) = *reinterpret_cast<uint2*>(h);
}

// ---------------------------------------------------------------------------
// Kernel 2: pipelined HMMA GEMM. CTA 128x128, warp 64x32 (2m x 4n).
// 2 macro-steps of K64, double-buffered. Rows 64 fp16 = 128B,
// 16B-chunk XOR swizzle (ch ^ (row&7)).
// ---------------------------------------------------------------------------
#define CHUNK_A 16384
#define CHUNK_B 16384
#define BUF_BYTES (CHUNK_A + CHUNK_B)   // 32KB per stage
#define SMEM_BYTES (2 * BUF_BYTES)      // 64KB

__global__ __launch_bounds__(256, 2)
void cosine_hmma_kernel(float* __restrict__ out) {
    extern __shared__ __align__(1024) char smem[];

    int tid  = threadIdx.x;
    int wid  = tid >> 5;
    int lane = tid & 31;

    int p  = blockIdx.z;          // (b*4+i)*5 + j
    int b  = p / 20;
    int ij = p % 20;
    int i  = ij / 5;
    int j  = ij % 5;
    int m0 = blockIdx.y * 128;
    int n0 = blockIdx.x * 128;

    const __half* abase = g_qs + (size_t)((b * 4 + i) * 1024 + m0) * KDIM;
    const __half* bbase = g_ss + (size_t)((b * 5 + j) * 1024 + n0) * KDIM;

    uint32_t smem0 = smem_u32(smem);

    auto load_step = [&](int s) {
        uint32_t bufA = smem0 + (uint32_t)(s & 1) * BUF_BYTES;
        uint32_t bufB = bufA + CHUNK_A;
        int col = s * 64;
        #pragma unroll
        for (int it = 0; it < 4; it++) {
            int lin = tid + it * 256;    // 0..1023
            int row = lin >> 3;          // 0..127
            int ch  = lin & 7;           // 16B chunks of 128B row
            uint32_t doff = (uint32_t)row * 128u + (uint32_t)((ch ^ (row & 7)) << 4);
            CP_ASYNC16(bufA + doff, abase + (size_t)row * KDIM + col + ch * 8);
            CP_ASYNC16(bufB + doff, bbase + (size_t)row * KDIM + col + ch * 8);
        }
        CP_COMMIT();
    };

    // ---- warp tiling: 2 warps over m (64), 4 over n (32) ----
    int wm = wid & 1;
    int wn = wid >> 1;
    int mbase = wm * 64;
    int nbase = wn * 32;

    int a_mi   = lane >> 3;
    int a_row0 = mbase + (a_mi & 1) * 8 + (lane & 7);         // + mt*16
    int a_koff = (a_mi >> 1) * 8;
    int b_row0 = nbase + ((lane >> 4) & 1) * 8 + (lane & 7);  // + nt2*16
    int b_koff = ((lane >> 3) & 1) * 8;

    float acc[4][4][4];
    #pragma unroll
    for (int mt = 0; mt < 4; mt++)
        #pragma unroll
        for (int nt = 0; nt < 4; nt++)
            #pragma unroll
            for (int e = 0; e < 4; e++)
                acc[mt][nt][e] = 0.0f;

    auto mma_stage = [&](int s) {
        uint32_t bufA = smem0 + (uint32_t)(s & 1) * BUF_BYTES;
        uint32_t bufB = bufA + CHUNK_A;
        #pragma unroll
        for (int ks = 0; ks < 4; ks++) {
            int ka = ks * 16 + a_koff;
            int kb = ks * 16 + b_koff;

            uint32_t aF[4][4];
            #pragma unroll
            for (int mt = 0; mt < 4; mt++) {
                int row = a_row0 + mt * 16;
                uint32_t addr = bufA + (uint32_t)row * 128u
                              + (uint32_t)((((ka >> 3) ^ (row & 7)) << 4));
                ldm_x4(aF[mt], addr);
            }
            uint32_t bF[2][4];
            #pragma unroll
            for (int nt2 = 0; nt2 < 2; nt2++) {
                int row = b_row0 + nt2 * 16;
                uint32_t addr = bufB + (uint32_t)row * 128u
                              + (uint32_t)((((kb >> 3) ^ (row & 7)) << 4));
                ldm_x4(bF[nt2], addr);
            }

            #pragma unroll
            for (int mt = 0; mt < 4; mt++)
                #pragma unroll
                for (int nt = 0; nt < 4; nt++)
                    mma16816(acc[mt][nt], aF[mt], &bF[nt >> 1][(nt & 1) * 2]);
        }
    };

    // ---- 2-stage pipeline, one sync per stage ----
    load_step(0);
    load_step(1);

    CP_WAIT(1);
    __syncthreads();
    mma_stage(0);

    CP_WAIT(0);
    __syncthreads();
    mma_stage(1);

    // ---- Epilogue: direct fragment stores (32B contiguous per quad) ----
    int tr  = lane >> 2;
    int tc2 = (lane & 3) * 2;
    size_t obase = ((size_t)p << 20)
                 + (size_t)(m0 + mbase) * 1024 + (n0 + nbase);
    #pragma unroll
    for (int mt = 0; mt < 4; mt++) {
        #pragma unroll
        for (int nt = 0; nt < 4; nt++) {
            float* r0 = out + obase + (size_t)(mt * 16 + tr) * 1024 + nt * 8 + tc2;
            *reinterpret_cast<float2*>(r0) =
                make_float2(acc[mt][nt][0], acc[mt][nt][1]);
            *reinterpret_cast<float2*>(r0 + 8 * 1024) =
                make_float2(acc[mt][nt][2], acc[mt][nt][3]);
        }
    }
}

extern "C" void kernel_launch(void* const* d_in, const int* in_sizes, int n_in,
                              void* d_out, int out_size) {
    const float* support = (const float*)d_in[0];
    const float* query   = (const float*)d_in[1];
    float* out = (float*)d_out;

    cudaFuncSetAttribute(cosine_hmma_kernel,
                         cudaFuncAttributeMaxDynamicSharedMemorySize, SMEM_BYTES);

    int total_rows = NQ_ROWS + NS_ROWS;
    int blocks1 = (total_rows + 7) / 8;
    normalize_kernel<<<blocks1, 256>>>(support, query);

    dim3 grid(8, 8, 40);
    cosine_hmma_kernel<<<grid, 256, SMEM_BYTES>>>(out);
}

// round 12
// speedup vs baseline: 1.5824x; 1.0570x over previous
#include <cuda_runtime.h>
#include <cuda_fp16.h>
#include <cstdint>

// support: (2,5,1024,128) -> d_in[0]
// query:   (2,4,1024,128) -> d_in[1]
// out:     (2,4,5,1024,1024) fp32
// sim[b,i,j,m,n] = <q_norm[b,i,m,:], s_norm[b,j,n,:]>
//
// Single-pass fp16 HMMA (rel_err ~2.9e-4 measured).
// CTA tile 128x128 with ONLY 4 warps (128 threads), warp tile 64x64
// (2x2 warp grid) -> fragment duplication dupA=dupB=2, i.e. 16KB smem
// reads per k16 slice instead of 24KB (-33% L1 traffic, the measured
// binding resource). 2 macro-steps of K64, double-buffered cp.async,
// 64KB smem/CTA -> 2 CTAs/SM, ~180 regs/thread (cap 256 at 2x128 thr).

#define NQ_ROWS 8192
#define NS_ROWS 10240
#define KDIM 128

__device__ __align__(16) __half g_qs[NQ_ROWS * KDIM];
__device__ __align__(16) __half g_ss[NS_ROWS * KDIM];

__device__ __forceinline__ uint32_t smem_u32(const void* p) {
    uint32_t a;
    asm("{ .reg .u64 t; cvta.to.shared.u64 t, %1; cvt.u32.u64 %0, t; }"
        : "=r"(a) : "l"(p));
    return a;
}

__device__ __forceinline__ void ldm_x4(uint32_t* r, uint32_t addr) {
    asm volatile("ldmatrix.sync.aligned.m8n8.x4.shared.b16 {%0,%1,%2,%3}, [%4];"
        : "=r"(r[0]), "=r"(r[1]), "=r"(r[2]), "=r"(r[3]) : "r"(addr));
}

__device__ __forceinline__ void mma16816(float* d, const uint32_t* a,
                                         const uint32_t* b) {
    asm volatile(
        "mma.sync.aligned.m16n8k16.row.col.f32.f16.f16.f32 "
        "{%0,%1,%2,%3}, {%4,%5,%6,%7}, {%8,%9}, {%0,%1,%2,%3};"
        : "+f"(d[0]), "+f"(d[1]), "+f"(d[2]), "+f"(d[3])
        : "r"(a[0]), "r"(a[1]), "r"(a[2]), "r"(a[3]), "r"(b[0]), "r"(b[1]));
}

#define CP_ASYNC16(dst, src) \
    asm volatile("cp.async.cg.shared.global [%0], [%1], 16;" \
        :: "r"(dst), "l"(src) : "memory")
#define CP_COMMIT() asm volatile("cp.async.commit_group;" ::: "memory")
#define CP_WAIT(n)  asm volatile("cp.async.wait_group %0;" :: "n"(n) : "memory")

// ---------------------------------------------------------------------------
// Kernel 1: normalize rows -> fp16. One warp per row.
// ---------------------------------------------------------------------------
__global__ void normalize_kernel(const float* __restrict__ s,
                                 const float* __restrict__ q) {
    int warp_id = (blockIdx.x * blockDim.x + threadIdx.x) >> 5;
    int lane    = threadIdx.x & 31;
    if (warp_id >= NQ_ROWS + NS_ROWS) return;

    bool is_q = warp_id < NQ_ROWS;
    const float* src = is_q ? q + (size_t)warp_id * KDIM
                            : s + (size_t)(warp_id - NQ_ROWS) * KDIM;
    __half* dst = is_q ? g_qs + (size_t)warp_id * KDIM
                       : g_ss + (size_t)(warp_id - NQ_ROWS) * KDIM;

    float4 v = reinterpret_cast<const float4*>(src)[lane];
    float ssum = v.x * v.x + v.y * v.y + v.z * v.z + v.w * v.w;
    #pragma unroll
    for (int o = 16; o > 0; o >>= 1)
        ssum += __shfl_xor_sync(0xffffffffu, ssum, o);
    float rn = 1.0f / fmaxf(sqrtf(ssum), 1e-12f);

    __half h[4] = {__float2half_rn(v.x * rn), __float2half_rn(v.y * rn),
                   __float2half_rn(v.z * rn), __float2half_rn(v.w * rn)};
    *reinterpret_cast<uint2*>(dst + lane * 4) = *reinterpret_cast<uint2*>(h);
}

// ---------------------------------------------------------------------------
// Kernel 2: pipelined HMMA GEMM. CTA 128x128, 4 warps 2(m)x2(n),
// warp tile 64x64 (4 mt x 8 nt). 2 macro-steps of K64, double-buffered.
// Rows 64 fp16 = 128B, 16B-chunk XOR swizzle (ch ^ (row&7)).
// ---------------------------------------------------------------------------
#define CHUNK_A 16384
#define CHUNK_B 16384
#define BUF_BYTES (CHUNK_A + CHUNK_B)   // 32KB per stage
#define SMEM_BYTES (2 * BUF_BYTES)      // 64KB

__global__ __launch_bounds__(128, 2)
void cosine_hmma_kernel(float* __restrict__ out) {
    extern __shared__ __align__(1024) char smem[];

    int tid  = threadIdx.x;
    int wid  = tid >> 5;
    int lane = tid & 31;

    int p  = blockIdx.z;          // (b*4+i)*5 + j
    int b  = p / 20;
    int ij = p % 20;
    int i  = ij / 5;
    int j  = ij % 5;
    int m0 = blockIdx.y * 128;
    int n0 = blockIdx.x * 128;

    const __half* abase = g_qs + (size_t)((b * 4 + i) * 1024 + m0) * KDIM;
    const __half* bbase = g_ss + (size_t)((b * 5 + j) * 1024 + n0) * KDIM;

    uint32_t smem0 = smem_u32(smem);

    auto load_step = [&](int s) {
        uint32_t bufA = smem0 + (uint32_t)(s & 1) * BUF_BYTES;
        uint32_t bufB = bufA + CHUNK_A;
        int col = s * 64;
        // A: 1024 chunks, B: 1024 chunks; 128 threads -> 8 iters each.
        #pragma unroll
        for (int it = 0; it < 8; it++) {
            int lin = tid + it * 128;    // 0..1023
            int row = lin >> 3;          // 0..127
            int ch  = lin & 7;           // 16B chunks of 128B row
            uint32_t doff = (uint32_t)row * 128u + (uint32_t)((ch ^ (row & 7)) << 4);
            CP_ASYNC16(bufA + doff, abase + (size_t)row * KDIM + col + ch * 8);
            CP_ASYNC16(bufB + doff, bbase + (size_t)row * KDIM + col + ch * 8);
        }
        CP_COMMIT();
    };

    // ---- warp tiling: 2 warps over m (64 each), 2 over n (64 each) ----
    int wm = wid >> 1;
    int wn = wid & 1;
    int mbase = wm * 64;
    int nbase = wn * 64;

    int a_mi   = lane >> 3;
    int a_row0 = mbase + (a_mi & 1) * 8 + (lane & 7);         // + mt*16
    int a_koff = (a_mi >> 1) * 8;
    int b_row0 = nbase + ((lane >> 4) & 1) * 8 + (lane & 7);  // + nt2*16
    int b_koff = ((lane >> 3) & 1) * 8;

    float acc[4][8][4];
    #pragma unroll
    for (int mt = 0; mt < 4; mt++)
        #pragma unroll
        for (int nt = 0; nt < 8; nt++)
            #pragma unroll
            for (int e = 0; e < 4; e++)
                acc[mt][nt][e] = 0.0f;

    auto mma_stage = [&](int s) {
        uint32_t bufA = smem0 + (uint32_t)(s & 1) * BUF_BYTES;
        uint32_t bufB = bufA + CHUNK_A;
        #pragma unroll
        for (int ks = 0; ks < 4; ks++) {
            int ka = ks * 16 + a_koff;
            int kb = ks * 16 + b_koff;

            uint32_t aF[4][4];
            #pragma unroll
            for (int mt = 0; mt < 4; mt++) {
                int row = a_row0 + mt * 16;
                uint32_t addr = bufA + (uint32_t)row * 128u
                              + (uint32_t)((((ka >> 3) ^ (row & 7)) << 4));
                ldm_x4(aF[mt], addr);
            }
            uint32_t bF[4][4];
            #pragma unroll
            for (int nt2 = 0; nt2 < 4; nt2++) {
                int row = b_row0 + nt2 * 16;
                uint32_t addr = bufB + (uint32_t)row * 128u
                              + (uint32_t)((((kb >> 3) ^ (row & 7)) << 4));
                ldm_x4(bF[nt2], addr);
            }

            #pragma unroll
            for (int mt = 0; mt < 4; mt++)
                #pragma unroll
                for (int nt = 0; nt < 8; nt++)
                    mma16816(acc[mt][nt], aF[mt], &bF[nt >> 1][(nt & 1) * 2]);
        }
    };

    // ---- 2-stage pipeline, one sync per stage ----
    load_step(0);
    load_step(1);

    CP_WAIT(1);
    __syncthreads();
    mma_stage(0);

    CP_WAIT(0);
    __syncthreads();
    mma_stage(1);

    // ---- Epilogue: direct fragment stores (32B contiguous per quad) ----
    int tr  = lane >> 2;
    int tc2 = (lane & 3) * 2;
    size_t obase = ((size_t)p << 20)
                 + (size_t)(m0 + mbase) * 1024 + (n0 + nbase);
    #pragma unroll
    for (int mt = 0; mt < 4; mt++) {
        #pragma unroll
        for (int nt = 0; nt < 8; nt++) {
            float* r0 = out + obase + (size_t)(mt * 16 + tr) * 1024 + nt * 8 + tc2;
            *reinterpret_cast<float2*>(r0) =
                make_float2(acc[mt][nt][0], acc[mt][nt][1]);
            *reinterpret_cast<float2*>(r0 + 8 * 1024) =
                make_float2(acc[mt][nt][2], acc[mt][nt][3]);
        }
    }
}

extern "C" void kernel_launch(void* const* d_in, const int* in_sizes, int n_in,
                              void* d_out, int out_size) {
    const float* support = (const float*)d_in[0];
    const float* query   = (const float*)d_in[1];
    float* out = (float*)d_out;

    cudaFuncSetAttribute(cosine_hmma_kernel,
                         cudaFuncAttributeMaxDynamicSharedMemorySize, SMEM_BYTES);

    int total_rows = NQ_ROWS + NS_ROWS;
    int blocks1 = (total_rows + 7) / 8;
    normalize_kernel<<<blocks1, 256>>>(support, query);

    dim3 grid(8, 8, 40);
    cosine_hmma_kernel<<<grid, 128, SMEM_BYTES>>>(out);
}

// round 13
// speedup vs baseline: 1.6027x; 1.0128x over previous
#include <cuda_runtime.h>
#include <cuda_fp16.h>
#include <cstdint>

// support: (2,5,1024,128) -> d_in[0]
// query:   (2,4,1024,128) -> d_in[1]
// out:     (2,4,5,1024,1024) fp32
// sim[b,i,j,m,n] = <q_norm[b,i,m,:], s_norm[b,j,n,:]>
//
// Single-pass fp16 HMMA (rel_err ~2.9e-4 measured).
// CTA 128x128, 4 warps (2x2), warp tile 64x64. 2 macro-steps of K64,
// double-buffered cp.async. NEW in R13: fragment-level software pipeline —
// LDSMs for k-slice ks+1 issued before MMAs of slice ks (double-buffered
// fragment registers), so LDSM latency hides under tensor issue.

#define NQ_ROWS 8192
#define NS_ROWS 10240
#define KDIM 128

__device__ __align__(16) __half g_qs[NQ_ROWS * KDIM];
__device__ __align__(16) __half g_ss[NS_ROWS * KDIM];

__device__ __forceinline__ uint32_t smem_u32(const void* p) {
    uint32_t a;
    asm("{ .reg .u64 t; cvta.to.shared.u64 t, %1; cvt.u32.u64 %0, t; }"
        : "=r"(a) : "l"(p));
    return a;
}

__device__ __forceinline__ void ldm_x4(uint32_t* r, uint32_t addr) {
    asm volatile("ldmatrix.sync.aligned.m8n8.x4.shared.b16 {%0,%1,%2,%3}, [%4];"
        : "=r"(r[0]), "=r"(r[1]), "=r"(r[2]), "=r"(r[3]) : "r"(addr));
}

__device__ __forceinline__ void mma16816(float* d, const uint32_t* a,
                                         const uint32_t* b) {
    asm volatile(
        "mma.sync.aligned.m16n8k16.row.col.f32.f16.f16.f32 "
        "{%0,%1,%2,%3}, {%4,%5,%6,%7}, {%8,%9}, {%0,%1,%2,%3};"
        : "+f"(d[0]), "+f"(d[1]), "+f"(d[2]), "+f"(d[3])
        : "r"(a[0]), "r"(a[1]), "r"(a[2]), "r"(a[3]), "r"(b[0]), "r"(b[1]));
}

#define CP_ASYNC16(dst, src) \
    asm volatile("cp.async.cg.shared.global [%0], [%1], 16;" \
        :: "r"(dst), "l"(src) : "memory")
#define CP_COMMIT() asm volatile("cp.async.commit_group;" ::: "memory")
#define CP_WAIT(n)  asm volatile("cp.async.wait_group %0;" :: "n"(n) : "memory")

// ---------------------------------------------------------------------------
// Kernel 1: normalize rows -> fp16. One warp per row.
// ---------------------------------------------------------------------------
__global__ void normalize_kernel(const float* __restrict__ s,
                                 const float* __restrict__ q) {
    int warp_id = (blockIdx.x * blockDim.x + threadIdx.x) >> 5;
    int lane    = threadIdx.x & 31;
    if (warp_id >= NQ_ROWS + NS_ROWS) return;

    bool is_q = warp_id < NQ_ROWS;
    const float* src = is_q ? q + (size_t)warp_id * KDIM
                            : s + (size_t)(warp_id - NQ_ROWS) * KDIM;
    __half* dst = is_q ? g_qs + (size_t)warp_id * KDIM
                       : g_ss + (size_t)(warp_id - NQ_ROWS) * KDIM;

    float4 v = reinterpret_cast<const float4*>(src)[lane];
    float ssum = v.x * v.x + v.y * v.y + v.z * v.z + v.w * v.w;
    #pragma unroll
    for (int o = 16; o > 0; o >>= 1)
        ssum += __shfl_xor_sync(0xffffffffu, ssum, o);
    float rn = 1.0f / fmaxf(sqrtf(ssum), 1e-12f);

    __half h[4] = {__float2half_rn(v.x * rn), __float2half_rn(v.y * rn),
                   __float2half_rn(v.z * rn), __float2half_rn(v.w * rn)};
    *reinterpret_cast<uint2*>(dst + lane * 4) = *reinterpret_cast<uint2*>(h);
}

// ---------------------------------------------------------------------------
// Kernel 2: pipelined HMMA GEMM. CTA 128x128, 4 warps 2(m)x2(n),
// warp tile 64x64. 2 macro-steps of K64 double-buffered in smem;
// fragment double-buffering across the 4 k16 slices of each stage.
// Rows 64 fp16 = 128B, 16B-chunk XOR swizzle (ch ^ (row&7)).
// ---------------------------------------------------------------------------
#define CHUNK_A 16384
#define CHUNK_B 16384
#define BUF_BYTES (CHUNK_A + CHUNK_B)   // 32KB per stage
#define SMEM_BYTES (2 * BUF_BYTES)      // 64KB

__global__ __launch_bounds__(128, 2)
void cosine_hmma_kernel(float* __restrict__ out) {
    extern __shared__ __align__(1024) char smem[];

    int tid  = threadIdx.x;
    int wid  = tid >> 5;
    int lane = tid & 31;

    int p  = blockIdx.z;          // (b*4+i)*5 + j
    int b  = p / 20;
    int ij = p % 20;
    int i  = ij / 5;
    int j  = ij % 5;
    int m0 = blockIdx.y * 128;
    int n0 = blockIdx.x * 128;

    const __half* abase = g_qs + (size_t)((b * 4 + i) * 1024 + m0) * KDIM;
    const __half* bbase = g_ss + (size_t)((b * 5 + j) * 1024 + n0) * KDIM;

    uint32_t smem0 = smem_u32(smem);

    auto load_step = [&](int s) {
        uint32_t bufA = smem0 + (uint32_t)(s & 1) * BUF_BYTES;
        uint32_t bufB = bufA + CHUNK_A;
        int col = s * 64;
        #pragma unroll
        for (int it = 0; it < 8; it++) {
            int lin = tid + it * 128;    // 0..1023
            int row = lin >> 3;          // 0..127
            int ch  = lin & 7;           // 16B chunks of 128B row
            uint32_t doff = (uint32_t)row * 128u + (uint32_t)((ch ^ (row & 7)) << 4);
            CP_ASYNC16(bufA + doff, abase + (size_t)row * KDIM + col + ch * 8);
            CP_ASYNC16(bufB + doff, bbase + (size_t)row * KDIM + col + ch * 8);
        }
        CP_COMMIT();
    };

    // ---- warp tiling: 2 warps over m (64 each), 2 over n (64 each) ----
    int wm = wid >> 1;
    int wn = wid & 1;
    int mbase = wm * 64;
    int nbase = wn * 64;

    int a_mi   = lane >> 3;
    int a_row0 = mbase + (a_mi & 1) * 8 + (lane & 7);         // + mt*16
    int a_koff = (a_mi >> 1) * 8;
    int b_row0 = nbase + ((lane >> 4) & 1) * 8 + (lane & 7);  // + nt2*16
    int b_koff = ((lane >> 3) & 1) * 8;

    float acc[4][8][4];
    #pragma unroll
    for (int mt = 0; mt < 4; mt++)
        #pragma unroll
        for (int nt = 0; nt < 8; nt++)
            #pragma unroll
            for (int e = 0; e < 4; e++)
                acc[mt][nt][e] = 0.0f;

    // Double-buffered fragments (software pipeline across k16 slices).
    uint32_t aF[2][4][4];
    uint32_t bF[2][4][4];

    auto load_frags = [&](uint32_t bufA, uint32_t bufB, int ks, int fsel) {
        int ka = ks * 16 + a_koff;
        int kb = ks * 16 + b_koff;
        #pragma unroll
        for (int mt = 0; mt < 4; mt++) {
            int row = a_row0 + mt * 16;
            uint32_t addr = bufA + (uint32_t)row * 128u
                          + (uint32_t)((((ka >> 3) ^ (row & 7)) << 4));
            ldm_x4(aF[fsel][mt], addr);
        }
        #pragma unroll
        for (int nt2 = 0; nt2 < 4; nt2++) {
            int row = b_row0 + nt2 * 16;
            uint32_t addr = bufB + (uint32_t)row * 128u
                          + (uint32_t)((((kb >> 3) ^ (row & 7)) << 4));
            ldm_x4(bF[fsel][nt2], addr);
        }
    };

    auto mma_frags = [&](int fsel) {
        #pragma unroll
        for (int mt = 0; mt < 4; mt++)
            #pragma unroll
            for (int nt = 0; nt < 8; nt++)
                mma16816(acc[mt][nt], aF[fsel][mt],
                         &bF[fsel][nt >> 1][(nt & 1) * 2]);
    };

    auto mma_stage = [&](int s) {
        uint32_t bufA = smem0 + (uint32_t)(s & 1) * BUF_BYTES;
        uint32_t bufB = bufA + CHUNK_A;
        load_frags(bufA, bufB, 0, 0);
        #pragma unroll
        for (int ks = 0; ks < 4; ks++) {
            if (ks < 3)
                load_frags(bufA, bufB, ks + 1, (ks + 1) & 1);  // prefetch next
            mma_frags(ks & 1);
        }
    };

    // ---- 2-stage pipeline, one sync per stage ----
    load_step(0);
    load_step(1);

    CP_WAIT(1);
    __syncthreads();
    mma_stage(0);

    CP_WAIT(0);
    __syncthreads();
    mma_stage(1);

    // ---- Epilogue: direct fragment stores (32B contiguous per quad) ----
    int tr  = lane >> 2;
    int tc2 = (lane & 3) * 2;
    size_t obase = ((size_t)p << 20)
                 + (size_t)(m0 + mbase) * 1024 + (n0 + nbase);
    #pragma unroll
    for (int mt = 0; mt < 4; mt++) {
        #pragma unroll
        for (int nt = 0; nt < 8; nt++) {
            float* r0 = out + obase + (size_t)(mt * 16 + tr) * 1024 + nt * 8 + tc2;
            *reinterpret_cast<float2*>(r0) =
                make_float2(acc[mt][nt][0], acc[mt][nt][1]);
            *reinterpret_cast<float2*>(r0 + 8 * 1024) =
                make_float2(acc[mt][nt][2], acc[mt][nt][3]);
        }
    }
}

extern "C" void kernel_launch(void* const* d_in, const int* in_sizes, int n_in,
                              void* d_out, int out_size) {
    const float* support = (const float*)d_in[0];
    const float* query   = (const float*)d_in[1];
    float* out = (float*)d_out;

    cudaFuncSetAttribute(cosine_hmma_kernel,
                         cudaFuncAttributeMaxDynamicSharedMemorySize, SMEM_BYTES);

    int total_rows = NQ_ROWS + NS_ROWS;
    int blocks1 = (total_rows + 7) / 8;
    normalize_kernel<<<blocks1, 256>>>(support, query);

    dim3 grid(8, 8, 40);
    cosine_hmma_kernel<<<grid, 128, SMEM_BYTES>>>(out);
}